// round 12
// baseline (speedup 1.0000x reference)
#include <cuda_runtime.h>
#include <math.h>

#define N_NODES 8000
#define NT      (N_NODES * 12)        // 96000

// ---- k1 (reduce) ----
#define NBLK_R  100
#define CHUNK_R (N_NODES / NBLK_R)    // 80
#define SUBG    4
#define SUBCH   (CHUNK_R / SUBG)      // 20

// ---- k2 (apply) ----
#define NODES_PER_BLK 64
#define NBLK_M  (N_NODES / NODES_PER_BLK)   // 125
#define NTHREADS 320

// Row-per-block partials: rows 100..127 never written (static zero-init) ->
// k2's combine sums a fixed 128 rows in fixed order: deterministic.
__device__ float g_part[128][128];

// ================= k1: lean reduce (partials only, no tail) =================
__global__ void __launch_bounds__(SUBG * 128)
reduce_kernel(const float* __restrict__ x,
              const float* __restrict__ U1,
              const float* __restrict__ U2,   // (5,8000) row-major
              const float* __restrict__ U3)
{
    // Allow the dependent kernel to start launching; its preamble overlaps us.
    cudaTriggerProgrammaticLaunchCompletion();

    __shared__ float sAcc[SUBG][128];

    const int tid = threadIdx.x;
    const int j   = tid & 127;
    const int g   = tid >> 7;
    const int n0  = blockIdx.x * CHUNK_R + g * SUBCH;

    float acc = 0.f;
    if (j < 60) {
        #pragma unroll
        for (int i = 0; i < SUBCH; i++) {
            const int n = n0 + i;
            acc += x[n * 60 + j] * U1[n];
        }
    } else if (j < 120) {
        const int jj = j - 60;
        const int f2 = jj / 12;
        const int t  = jj % 12;
        float u3[5];
        #pragma unroll
        for (int f = 0; f < 5; f++) u3[f] = U3[f];
        #pragma unroll
        for (int i = 0; i < SUBCH; i++) {
            const int n = n0 + i;
            float r = 0.f;
            #pragma unroll
            for (int f = 0; f < 5; f++)
                r += x[n * 60 + t * 5 + f] * u3[f];   // same lines as lhs warps
            acc += U2[f2 * N_NODES + n] * r;
        }
    }
    sAcc[g][j] = acc;
    __syncthreads();

    if (g == 0 && j < 120)   // fixed-order subgroup combine, coalesced row store
        g_part[blockIdx.x][j] = sAcc[0][j] + sAcc[1][j] + sAcc[2][j] + sAcc[3][j];
    // kernel completion = the dependency k2's gridsync waits on
}

// ====== k2: preamble overlaps k1; gridsync; combine+At2; apply+conv ======
__global__ void __launch_bounds__(NTHREADS)
apply_kernel(const float* __restrict__ x,
             const float* __restrict__ be,
             const float* __restrict__ Ve,
             const float* __restrict__ w,     // conv2_w (5,5,1,3)
             const float* __restrict__ bias,  // conv2_b (5,)
             float* __restrict__ out)
{
    __shared__ float sX [NODES_PER_BLK][61];
    __shared__ float sX2[5][NODES_PER_BLK * 13];
    __shared__ float sQ[2][120];
    __shared__ float sLhs[60];
    __shared__ float sM2[60];
    __shared__ float sVe[144];
    __shared__ float sBe[144];
    __shared__ float sS[12][12];
    __shared__ float sE[12][12];
    __shared__ float sAt[12][12];
    __shared__ float sW[75];
    __shared__ float sB[5];

    const int tid = threadIdx.x;
    const int n0  = blockIdx.x * NODES_PER_BLK;

    // ---------- preamble: overlapped with k1 when PDL is active ----------
    {
        const float4* xp = (const float4*)(x + n0 * 60);
        #pragma unroll
        for (int r = 0; r < 3; r++) {
            const int j = tid + r * NTHREADS;
            float4 v = xp[j];
            const int n = j / 15, c = (j % 15) * 4;
            float* d = &sX[n][c];
            d[0] = v.x; d[1] = v.y; d[2] = v.z; d[3] = v.w;
        }
    }
    if (tid < 144)               sVe[tid]       = Ve[tid];
    if (tid >= 160 && tid < 304) sBe[tid - 160] = be[tid - 160];
    if (tid < 75)                sW[tid]        = w[tid];
    if (tid >= 96 && tid < 101)  sB[tid - 96]   = bias[tid - 96];

    // ---------- wait for k1 (full memory visibility of g_part) ----------
    cudaGridDependencySynchronize();
    __syncthreads();

    // ---------- combine: (half q, j) sums 64 fixed rows, coalesced ----------
    if (tid < 240) {
        const int q = tid / 120, j = tid % 120;
        const float* p = &g_part[q * 64][0];
        float s = 0.f;
        #pragma unroll 16
        for (int i = 0; i < 64; i++)
            s += __ldcg(p + i * 128 + j);       // rows 100..127 read as 0
        sQ[q][j] = s;
    }
    __syncthreads();
    if (tid < 120) {
        float s = sQ[0][tid] + sQ[1][tid];
        if (tid < 60) sLhs[tid] = s;
        else          sM2[tid - 60] = s;
    }
    __syncthreads();

    // ---------- At2 distributed: 144-thread phases ----------
    if (tid < 144) {
        const int t1 = tid / 12, t2 = tid % 12;
        float p = 0.f;
        #pragma unroll
        for (int f = 0; f < 5; f++) p += sLhs[t1 * 5 + f] * sM2[f * 12 + t2];
        p += sBe[tid];
        sS[t1][t2] = 1.f / (1.f + __expf(-p));
    }
    __syncthreads();
    if (tid < 144) {
        const int t1 = tid / 12, t2 = tid % 12;
        float e = 0.f;
        #pragma unroll
        for (int k = 0; k < 12; k++) e += sVe[t1 * 12 + k] * sS[k][t2];
        sE[t1][t2] = e;
    }
    __syncthreads();
    if (tid < 12) {                               // column softmax
        const int t2 = tid;
        float E[12];
        float mx = -1e30f;
        #pragma unroll
        for (int k = 0; k < 12; k++) { E[k] = sE[k][t2]; mx = fmaxf(mx, E[k]); }
        float den = 0.f;
        #pragma unroll
        for (int k = 0; k < 12; k++) { E[k] = __expf(E[k] - mx); den += E[k]; }
        const float inv = 1.f / den;
        #pragma unroll
        for (int k = 0; k < 12; k++) sAt[k][t2] = E[k] * inv;
    }
    __syncthreads();

    // ---------- Phase B: thread (f, nl) -> x2[f][nl][0..11] ----------
    {
        const int f  = tid / NODES_PER_BLK;
        const int nl = tid % NODES_PER_BLK;
        float xr[12];
        #pragma unroll
        for (int tp = 0; tp < 12; tp++) xr[tp] = sX[nl][tp * 5 + f];
        float* dst = &sX2[f][nl * 13];
        #pragma unroll
        for (int t = 0; t < 12; t++) {
            float a = 0.f;
            #pragma unroll
            for (int tp = 0; tp < 12; tp++) a += xr[tp] * sAt[tp][t];
            dst[t] = a;
        }
    }
    __syncthreads();

    // ---------- Phase C: thread (o, nl) -> conv plane + 48B store ----------
    {
        const int o  = tid / NODES_PER_BLK;
        const int nl = tid % NODES_PER_BLK;
        float wr[15];
        #pragma unroll
        for (int i = 0; i < 15; i++) wr[i] = sW[o * 15 + i];
        const float b0 = sB[o];

        float yr[12];
        #pragma unroll
        for (int t = 0; t < 12; t++) yr[t] = b0;
        #pragma unroll
        for (int fi = 0; fi < 5; fi++) {
            const float* s = &sX2[fi][nl * 13];
            float v[12];
            #pragma unroll
            for (int t = 0; t < 12; t++) v[t] = s[t];
            const float w0 = wr[fi * 3 + 0], w1 = wr[fi * 3 + 1], w2 = wr[fi * 3 + 2];
            #pragma unroll
            for (int t = 0; t < 12; t++) {
                float a = w1 * v[t];
                if (t > 0)  a += w0 * v[t - 1];
                if (t < 11) a += w2 * v[t + 1];
                yr[t] += a;
            }
        }
        // raw-reshape output: flat = o*N*T + n*T + t
        float4* op = (float4*)(out + o * NT + (n0 + nl) * 12);
        op[0] = make_float4(yr[0], yr[1], yr[2],  yr[3]);
        op[1] = make_float4(yr[4], yr[5], yr[6],  yr[7]);
        op[2] = make_float4(yr[8], yr[9], yr[10], yr[11]);
    }
}

extern "C" void kernel_launch(void* const* d_in, const int* in_sizes, int n_in,
                              void* d_out, int out_size)
{
    // metadata order: x, adj, U1_1, U2_1, U3_1, be_1, Ve_1,
    //                 U1_2, U2_2, U3_2, be_2, Ve_2,
    //                 conv1_w, conv1_b, conv2_w, conv2_b, W_hgc, b_hgc
    const float* x    = (const float*)d_in[0];
    const float* U1_2 = (const float*)d_in[7];
    const float* U2_2 = (const float*)d_in[8];
    const float* U3_2 = (const float*)d_in[9];
    const float* be_2 = (const float*)d_in[10];
    const float* Ve_2 = (const float*)d_in[11];
    const float* c2w  = (const float*)d_in[14];
    const float* c2b  = (const float*)d_in[15];
    float* out = (float*)d_out;

    // Hyperbolic branch contributes exactly 0.0*finite -> skipped entirely.
    reduce_kernel<<<NBLK_R, SUBG * 128>>>(x, U1_2, U2_2, U3_2);

    // PDL: k2 launches while k1 runs; preamble overlaps, gridsync orders.
    cudaLaunchConfig_t cfg = {};
    cfg.gridDim  = dim3(NBLK_M);
    cfg.blockDim = dim3(NTHREADS);
    cfg.dynamicSmemBytes = 0;
    cfg.stream = 0;                      // legacy default stream (same as <<<>>>)
    cudaLaunchAttribute attr[1];
    attr[0].id = cudaLaunchAttributeProgrammaticStreamSerialization;
    attr[0].val.programmaticStreamSerializationAllowed = 1;
    cfg.attrs = attr;
    cfg.numAttrs = 1;
    cudaError_t err = cudaLaunchKernelEx(&cfg, apply_kernel,
                                         x, be_2, Ve_2, c2w, c2b, out);
    if (err != cudaSuccess) {
        // Fallback: plain serialized launch. gridsync is trivially satisfied
        // (dependency complete at launch), so the kernel remains correct.
        apply_kernel<<<NBLK_M, NTHREADS>>>(x, be_2, Ve_2, c2w, c2b, out);
    }
}